// round 11
// baseline (speedup 1.0000x reference)
#include <cuda_runtime.h>
#include <math.h>

#define FULL 0xffffffffu
#define SENT 0xFFFFFFFFFFFFFFFFull

// Guaranteed single-MUFU approx ops (independent of compiler fast-math flags).
__device__ __forceinline__ float fast_sqrt(float x) {
    float r; asm("sqrt.approx.f32 %0, %1;" : "=f"(r) : "f"(x)); return r;
}
__device__ __forceinline__ float fast_rcp(float x) {
    float r; asm("rcp.approx.f32 %0, %1;" : "=f"(r) : "f"(x)); return r;
}
__device__ __forceinline__ unsigned long long ld_cg_u64(const unsigned long long* p) {
    unsigned long long v;
    asm volatile("ld.global.cg.u64 %0, [%1];" : "=l"(v) : "l"(p));
    return v;
}

// Global scratch. Statically consistent; the finalizer / last block restore all
// of it so every graph replay sees identical initial state.
__device__ double g_sum0 = 0.0, g_sum1 = 0.0;
__device__ int    g_cnt = 0, g_rdone = 0, g_bdone = 0;
__device__ unsigned long long g_mean_bits = SENT;   // packed {mean1,mean0}, SENT = not ready

__device__ __forceinline__ void acc_ray(float x, float y, float z,
                                        float cx, float cy, float cz, float c2,
                                        float& s0, float& s1, int& c) {
    float dt = x * cx + y * cy + z * cz;
    float un = dt * dt - c2;
    if (un > 0.f) {
        float sq = fast_sqrt(un);
        s0 += -sq - dt; s1 += sq - dt; c++;
    }
}

// Fused kernel: blocks [0, rblk) first perform the global hit-mean reduction and
// publish it; all miss-ray warps spin (cheap ld.cg poll) until published.
// Reducer blocks are the lowest block ids => resident in wave 1 => no deadlock.
__global__ __launch_bounds__(256, 8) void k_fused(const float* __restrict__ rd,
                                                  const float* __restrict__ cam,
                                                  const float* __restrict__ trand,
                                                  float* __restrict__ ns,
                                                  float* __restrict__ zs,
                                                  float* __restrict__ wout,
                                                  int P, int rblk, int nblocks) {
    __shared__ float2 scum[8][32];   // per-warp cum[64] (2/lane)
    __shared__ float2 sstp[8][32];   // per-warp steps[64]
    __shared__ float4 sns[8][32];    // per-warp new_samples staging (padded 3->4)
    __shared__ float  sh0[8], sh1[8];
    __shared__ int    shc[8];

    const int tid  = threadIdx.x;
    const int lane = tid & 31;
    const int wrp  = tid >> 5;

    float cx = cam[0], cy = cam[1], cz = cam[2];
    float c2 = cx * cx + cy * cy + cz * cz - 1.0f;   // R_SPHERE = 1

    // ---------------- Phase A: reduction (blocks < rblk) ----------------
    if ((int)blockIdx.x < rblk) {
        int i = ((int)blockIdx.x * 256 + tid) * 4;
        float s0 = 0.f, s1 = 0.f; int c = 0;
        if (i + 3 < P) {
            const float4* p4 = (const float4*)(rd + 3 * i);   // 16 | 48i bytes
            float4 A = p4[0], B = p4[1], C = p4[2];
            acc_ray(A.x, A.y, A.z, cx, cy, cz, c2, s0, s1, c);
            acc_ray(A.w, B.x, B.y, cx, cy, cz, c2, s0, s1, c);
            acc_ray(B.z, B.w, C.x, cx, cy, cz, c2, s0, s1, c);
            acc_ray(C.y, C.z, C.w, cx, cy, cz, c2, s0, s1, c);
        } else {
            for (int r = 0; r < 4 && i + r < P; r++) {
                int ii = i + r;
                acc_ray(rd[3*ii], rd[3*ii+1], rd[3*ii+2], cx, cy, cz, c2, s0, s1, c);
            }
        }
        #pragma unroll
        for (int d = 16; d; d >>= 1) {
            s0 += __shfl_down_sync(FULL, s0, d);
            s1 += __shfl_down_sync(FULL, s1, d);
            c  += __shfl_down_sync(FULL, c, d);
        }
        if (lane == 0) { sh0[wrp] = s0; sh1[wrp] = s1; shc[wrp] = c; }
        __syncthreads();
        if (tid == 0) {
            float a0 = 0.f, a1 = 0.f; int ac = 0;
            #pragma unroll
            for (int j = 0; j < 8; j++) { a0 += sh0[j]; a1 += sh1[j]; ac += shc[j]; }
            atomicAdd(&g_sum0, (double)a0);
            atomicAdd(&g_sum1, (double)a1);
            atomicAdd(&g_cnt, ac);
            __threadfence();
            int t = atomicAdd(&g_rdone, 1);
            if (t == rblk - 1) {
                double t0 = atomicAdd(&g_sum0, 0.0);
                double t1 = atomicAdd(&g_sum1, 0.0);
                int    nc = atomicAdd(&g_cnt, 0);
                int nh = nc > 0 ? nc : 1;
                float m0 = (float)(t0 / (double)nh);
                float m1 = (float)(t1 / (double)nh);
                // reset accumulators for next replay (nobody reads them anymore)
                g_sum0 = 0.0; g_sum1 = 0.0; g_cnt = 0; g_rdone = 0;
                __threadfence();
                unsigned long long packed =
                    ((unsigned long long)__float_as_uint(m1) << 32) | __float_as_uint(m0);
                atomicExch(&g_mean_bits, packed);   // publish (release via fence above)
            }
        }
        // no block-wide sync needed before phase B: phase B smem is per-warp only
    }

    // ---------------- Phase B: main, one warp per ray ----------------
    int ray = (int)blockIdx.x * 8 + wrp;
    if (ray < P) {
        float x = rd[3 * ray + 0], y = rd[3 * ray + 1], z = rd[3 * ray + 2];
        float dt = x * cx + y * cy + z * cz;
        float un = dt * dt - c2;

        float si0, si1;
        if (un > 0.f) {
            float sq = fast_sqrt(un);
            si0 = -sq - dt; si1 = sq - dt;
        } else {
            unsigned long long mb;
            if (lane == 0) {
                mb = ld_cg_u64(&g_mean_bits);
                while (mb == SENT) { __nanosleep(200); mb = ld_cg_u64(&g_mean_bits); }
            }
            mb  = __shfl_sync(FULL, mb, 0);
            si0 = __uint_as_float((unsigned)(mb & 0xFFFFFFFFu));
            si1 = __uint_as_float((unsigned)(mb >> 32));
        }
        si0 = fmaxf(si0, 0.f); si1 = fmaxf(si1, 0.f);
        float mind = si0;
        float rng  = si1 - si0;
        float sd   = rng * (1.0f / 64.0f);

        float2 tr = *(const float2*)(trand + (unsigned)ray * 64u + 2u * (unsigned)lane);
        int i0 = 2 * lane, i1 = 2 * lane + 1;
        float st0 = mind + ((float)i0 * (1.0f / 63.0f)) * rng + (tr.x - 0.5f) * sd;
        float st1 = mind + ((float)i1 * (1.0f / 63.0f)) * rng + (tr.y - 0.5f) * sd;

        // SDF at both steps
        float px = cx + st0 * x, py = cy + st0 * y, pz = cz + st0 * z;
        float s_0 = fast_sqrt(px * px + py * py + pz * pz) - 0.5f;
        px = cx + st1 * x; py = cy + st1 * y; pz = cz + st1 * z;
        float s_1 = fast_sqrt(px * px + py * py + pz * pz) - 0.5f;

        // alpha via sigmoid-ratio identity:
        //   alpha_k = (sig_k - sig_{k+1}) / sig_k = (E_{k+1} - E_k) / (1 + E_{k+1}),
        //   E = exp(-sdf * inv_s).  Ratio provably < 1, so only clamp at 0.
        const float inv_s = 20.085536923187668f;  // exp(0.3 * 10)
        float E0 = __expf(-s_0 * inv_s);
        float E1 = __expf(-s_1 * inv_s);
        float En = __shfl_down_sync(FULL, E0, 1);  // E of step 2l+2
        float a0 = fmaxf(__fdividef(E1 - E0, 1.0f + E1), 0.f);
        float a1 = (lane < 31) ? fmaxf(__fdividef(En - E1, 1.0f + En), 0.f) : 0.f;

        float g0 = 1.0f - a0 + 1e-7f;
        float g1 = (lane < 31) ? (1.0f - a1 + 1e-7f) : 1.0f;

        // exclusive prefix-product across warp of per-lane pair product
        float pi = g0 * g1;
        #pragma unroll
        for (int d = 1; d < 32; d <<= 1) {
            float v = __shfl_up_sync(FULL, pi, d);
            if (lane >= d) pi *= v;
        }
        float Pex = __shfl_up_sync(FULL, pi, 1);
        if (lane == 0) Pex = 1.0f;

        float w0 = a0 * Pex;            // weights[2l]
        float w1 = a1 * (Pex * g0);     // weights[2l+1] (unused for lane 31)

        // unnormalized CDF (cumsum of w + 1e-8); element 63 contributes 0
        float e0 = w0 + 1e-8f;
        float e1 = (lane < 31) ? (w1 + 1e-8f) : 0.f;
        float qi = e0 + e1;
        #pragma unroll
        for (int d = 1; d < 32; d <<= 1) {
            float v = __shfl_up_sync(FULL, qi, d);
            if (lane >= d) qi += v;
        }
        float cum0  = qi - e1;                   // cumw[2l]  (exclusive shuffle eliminated)
        float cum1  = qi;                        // cumw[2l+1]
        float total = __shfl_sync(FULL, qi, 31);

        scum[wrp][lane] = make_float2(cum0, cum1);
        sstp[wrp][lane] = make_float2(st0, st1);
        __syncwarp();
        const float* cumA = (const float*)scum[wrp];
        const float* stpA = (const float*)sstp[wrp];

        // write weights (63 per ray)
        unsigned wbase = (unsigned)ray * 63u;
        wout[wbase + i0] = w0;
        if (lane < 31) wout[wbase + i1] = w1;

        // importance sample: one u per lane, u = (2l+1)/64
        float u  = (float)(2 * lane + 1) * (1.0f / 64.0f);
        float uT = u * total;

        // c = count of cumw[k] <= uT, k in [0,63). cumA[62]=total > uT => c <= 62.
        int c = 0;
        #pragma unroll
        for (int s = 32; s; s >>= 1) {
            if (cumA[c + s - 1] <= uT) c += s;
        }
        int   ab   = c + 1;                      // <= 63, no clamp needed
        float rtot = fast_rcp(total);
        float cdfb = (c == 0) ? 0.f : cumA[c - 1] * rtot;
        float cdfa = cumA[ab - 1] * rtot;
        float binb = stpA[c];
        float bina = stpA[ab];
        float den  = cdfa - cdfb;
        den = (den < 1e-8f) ? 1.0f : den;
        float zv = binb + __fdividef(u - cdfb, den) * (bina - binb);

        // z_samples (coalesced)
        zs[(unsigned)ray * 32u + (unsigned)lane] = zv;

        // new_samples via smem float4 staging -> 3 coalesced 128B stores
        float nx = fmaf(zv, x, cx);
        float ny = fmaf(zv, y, cy);
        float nz = fmaf(zv, z, cz);
        sns[wrp][lane] = make_float4(nx, ny, nz, 0.f);
        __syncwarp();
        const float* nsrc = (const float*)sns[wrp];
        unsigned nbase = (unsigned)ray * 96u;
        #pragma unroll
        for (int j = 0; j < 3; j++) {
            int e = 32 * j + lane;
            ns[nbase + e] = nsrc[e + e / 3];
        }
    }

    // ---------------- Phase C: globally-last block restores the sentinel ----------------
    __syncthreads();
    if (tid == 0) {
        __threadfence();
        int d = atomicAdd(&g_bdone, 1);
        if (d == nblocks - 1) {
            atomicExch(&g_bdone, 0);
            atomicExch(&g_mean_bits, SENT);   // ready for next graph replay
            __threadfence();
        }
    }
}

extern "C" void kernel_launch(void* const* d_in, const int* in_sizes, int n_in,
                              void* d_out, int out_size) {
    const float* rd  = (const float*)d_in[0];   // ray_dirs (1, P, 3)
    const float* cam = (const float*)d_in[1];   // cam_loc (1, 3)
    const float* tr  = (const float*)d_in[2];   // t_rand (P, 64)
    int P = in_sizes[0] / 3;

    float* out = (float*)d_out;
    float* ns  = out;                                     // (P, 32, 3)
    float* zs  = out + (size_t)P * 96;                    // (P, 32)
    float* wo  = out + (size_t)P * 96 + (size_t)P * 32;   // (P, 63)

    int nblocks = (P + 7) / 8;          // 8 rays (warps) per block
    int rblk    = (P + 1023) / 1024;    // reducer blocks: 4 rays/thread, 256 thr
    k_fused<<<nblocks, 256>>>(rd, cam, tr, ns, zs, wo, P, rblk, nblocks);
}

// round 13
// speedup vs baseline: 1.2899x; 1.2899x over previous
#include <cuda_runtime.h>
#include <math.h>

#define FULL 0xffffffffu

// Guaranteed single-MUFU approx ops (independent of compiler fast-math flags).
__device__ __forceinline__ float fast_sqrt(float x) {
    float r; asm("sqrt.approx.f32 %0, %1;" : "=f"(r) : "f"(x)); return r;
}
__device__ __forceinline__ float fast_rcp(float x) {
    float r; asm("rcp.approx.f32 %0, %1;" : "=f"(r) : "f"(x)); return r;
}

// Global-reduction scratch. Statically zero; the k_reduce finalizer resets it
// after use so every graph replay sees the same initial state.
__device__ double g_sum0 = 0.0, g_sum1 = 0.0;
__device__ int    g_cnt = 0, g_done = 0;
__device__ float  g_mean0 = 0.f, g_mean1 = 0.f;

__device__ __forceinline__ void acc_ray(float x, float y, float z,
                                        float cx, float cy, float cz, float c2,
                                        float& s0, float& s1, int& c) {
    float dt = x * cx + y * cy + z * cz;
    float un = dt * dt - c2;
    if (un > 0.f) {
        float sq = fast_sqrt(un);
        s0 += -sq - dt; s1 += sq - dt; c++;
    }
}

// Pass 1: 4 rays/thread, float4 loads. Reduce sum(si0), sum(si1), hit count.
__global__ __launch_bounds__(256) void k_reduce(const float* __restrict__ rd,
                                                const float* __restrict__ cam, int P) {
    int i = (blockIdx.x * blockDim.x + threadIdx.x) * 4;
    float cx = cam[0], cy = cam[1], cz = cam[2];
    float c2 = cx * cx + cy * cy + cz * cz - 1.0f;  // R_SPHERE = 1
    float s0 = 0.f, s1 = 0.f; int c = 0;
    if (i + 3 < P) {
        const float4* p4 = (const float4*)(rd + 3 * i);   // 48B-aligned (16 | 48i)
        float4 A = p4[0], B = p4[1], C = p4[2];
        acc_ray(A.x, A.y, A.z, cx, cy, cz, c2, s0, s1, c);
        acc_ray(A.w, B.x, B.y, cx, cy, cz, c2, s0, s1, c);
        acc_ray(B.z, B.w, C.x, cx, cy, cz, c2, s0, s1, c);
        acc_ray(C.y, C.z, C.w, cx, cy, cz, c2, s0, s1, c);
    } else {
        for (int r = 0; r < 4 && i + r < P; r++) {
            int ii = i + r;
            acc_ray(rd[3*ii], rd[3*ii+1], rd[3*ii+2], cx, cy, cz, c2, s0, s1, c);
        }
    }
    #pragma unroll
    for (int d = 16; d; d >>= 1) {
        s0 += __shfl_down_sync(FULL, s0, d);
        s1 += __shfl_down_sync(FULL, s1, d);
        c  += __shfl_down_sync(FULL, c, d);
    }
    __shared__ float sh0[8], sh1[8]; __shared__ int shc[8];
    int w = threadIdx.x >> 5, ln = threadIdx.x & 31;
    if (ln == 0) { sh0[w] = s0; sh1[w] = s1; shc[w] = c; }
    __syncthreads();
    if (threadIdx.x == 0) {
        float a0 = 0.f, a1 = 0.f; int ac = 0;
        #pragma unroll
        for (int j = 0; j < 8; j++) { a0 += sh0[j]; a1 += sh1[j]; ac += shc[j]; }
        atomicAdd(&g_sum0, (double)a0);
        atomicAdd(&g_sum1, (double)a1);
        atomicAdd(&g_cnt, ac);
        __threadfence();
        int t = atomicAdd(&g_done, 1);
        if (t == (int)gridDim.x - 1) {
            double t0 = atomicAdd(&g_sum0, 0.0);
            double t1 = atomicAdd(&g_sum1, 0.0);
            int    nc = atomicAdd(&g_cnt, 0);
            int nh = nc > 0 ? nc : 1;
            g_mean0 = (float)(t0 / (double)nh);
            g_mean1 = (float)(t1 / (double)nh);
            __threadfence();
            g_sum0 = 0.0; g_sum1 = 0.0; g_cnt = 0; g_done = 0;  // reset for next replay
        }
    }
}

// Pass 2: one warp per ray. Lane l owns steps {2l, 2l+1}.
__global__ __launch_bounds__(256) void k_main(const float* __restrict__ rd,
                                              const float* __restrict__ cam,
                                              const float* __restrict__ trand,
                                              float* __restrict__ ns,
                                              float* __restrict__ zs,
                                              float* __restrict__ wout, int P) {
    __shared__ float2 scum[8][32];   // per-warp cum[64] (2/lane)
    __shared__ float2 sstp[8][32];   // per-warp steps[64]
    __shared__ float4 sns[8][32];    // per-warp new_samples staging (padded 3->4)

    int gt   = blockIdx.x * blockDim.x + threadIdx.x;
    int ray  = gt >> 5;
    int lane = gt & 31;
    int wid  = (threadIdx.x >> 5);
    if (ray >= P) return;

    float cx = cam[0], cy = cam[1], cz = cam[2];
    float c2 = cx * cx + cy * cy + cz * cz - 1.0f;
    float x = rd[3 * ray + 0], y = rd[3 * ray + 1], z = rd[3 * ray + 2];
    float dt = x * cx + y * cy + z * cz;
    float un = dt * dt - c2;

    float si0, si1;
    if (un > 0.f) {
        float sq = fast_sqrt(un);
        si0 = -sq - dt; si1 = sq - dt;
    } else {
        si0 = g_mean0;
        si1 = g_mean1;
    }
    si0 = fmaxf(si0, 0.f); si1 = fmaxf(si1, 0.f);
    float mind = si0;
    float rng  = si1 - si0;
    float sd   = rng * (1.0f / 64.0f);

    // steps (coalesced float2 load of t_rand)
    float2 tr = *(const float2*)(trand + (unsigned)ray * 64u + 2u * (unsigned)lane);
    int i0 = 2 * lane, i1 = 2 * lane + 1;
    float st0 = mind + ((float)i0 * (1.0f / 63.0f)) * rng + (tr.x - 0.5f) * sd;
    float st1 = mind + ((float)i1 * (1.0f / 63.0f)) * rng + (tr.y - 0.5f) * sd;

    // SDF at both steps
    float px = cx + st0 * x, py = cy + st0 * y, pz = cz + st0 * z;
    float s_0 = fast_sqrt(px * px + py * py + pz * pz) - 0.5f;
    px = cx + st1 * x; py = cy + st1 * y; pz = cz + st1 * z;
    float s_1 = fast_sqrt(px * px + py * py + pz * pz) - 0.5f;

    // alpha via sigmoid-ratio identity:
    //   alpha_k = (sig_k - sig_{k+1}) / sig_k = (E_{k+1} - E_k) / (1 + E_{k+1}),
    //   E = exp(-sdf * inv_s). Ratio provably < 1, so only clamp at 0.
    const float inv_s = 20.085536923187668f;  // exp(0.3 * 10)
    float E0 = __expf(-s_0 * inv_s);
    float E1 = __expf(-s_1 * inv_s);
    float En = __shfl_down_sync(FULL, E0, 1);  // E of step 2l+2
    float a0 = fmaxf(__fdividef(E1 - E0, 1.0f + E1), 0.f);
    float a1 = (lane < 31) ? fmaxf(__fdividef(En - E1, 1.0f + En), 0.f) : 0.f;

    float g0 = 1.0f - a0 + 1e-7f;
    float g1 = (lane < 31) ? (1.0f - a1 + 1e-7f) : 1.0f;

    // exclusive prefix-product across warp of per-lane pair product
    float pi = g0 * g1;
    #pragma unroll
    for (int d = 1; d < 32; d <<= 1) {
        float v = __shfl_up_sync(FULL, pi, d);
        if (lane >= d) pi *= v;
    }
    float Pex = __shfl_up_sync(FULL, pi, 1);
    if (lane == 0) Pex = 1.0f;

    float w0 = a0 * Pex;            // weights[2l]
    float w1 = a1 * (Pex * g0);     // weights[2l+1] (unused for lane 31)

    // unnormalized CDF (cumsum of w + 1e-8); element 63 contributes 0
    float e0 = w0 + 1e-8f;
    float e1 = (lane < 31) ? (w1 + 1e-8f) : 0.f;
    float qi = e0 + e1;
    #pragma unroll
    for (int d = 1; d < 32; d <<= 1) {
        float v = __shfl_up_sync(FULL, qi, d);
        if (lane >= d) qi += v;
    }
    float cum0  = qi - e1;                   // cumw[2l]  (exclusive shuffle eliminated)
    float cum1  = qi;                        // cumw[2l+1]
    float total = __shfl_sync(FULL, qi, 31);

    // stash cum + steps in smem for the search
    scum[wid][lane] = make_float2(cum0, cum1);
    sstp[wid][lane] = make_float2(st0, st1);
    __syncwarp();
    const float* cumA = (const float*)scum[wid];
    const float* stpA = (const float*)sstp[wid];

    // write weights (63 per ray)
    unsigned wbase = (unsigned)ray * 63u;
    wout[wbase + i0] = w0;
    if (lane < 31) wout[wbase + i1] = w1;

    // importance sample: one u per lane, u = (2l+1)/64
    float u  = (float)(2 * lane + 1) * (1.0f / 64.0f);
    float uT = u * total;

    // c = count of cumw[k] <= uT, k in [0,63). cumA[62]=total > uT => c <= 62,
    // and k=c+s-1 <= 62 on every search iteration: no bounds guards needed.
    int c = 0;
    #pragma unroll
    for (int s = 32; s; s >>= 1) {
        if (cumA[c + s - 1] <= uT) c += s;
    }
    int   ab   = c + 1;                      // <= 63, no clamp needed
    float rtot = fast_rcp(total);
    float cdfb = (c == 0) ? 0.f : cumA[c - 1] * rtot;
    float cdfa = cumA[ab - 1] * rtot;
    float binb = stpA[c];
    float bina = stpA[ab];
    float den  = cdfa - cdfb;
    den = (den < 1e-8f) ? 1.0f : den;
    float zv = binb + __fdividef(u - cdfb, den) * (bina - binb);

    // z_samples (coalesced)
    zs[(unsigned)ray * 32u + (unsigned)lane] = zv;

    // new_samples: lane computes its own sample's coords, stage padded-4 in smem,
    // then 3 coalesced 128B stores. packed idx e -> padded idx e + e/3.
    float nx = fmaf(zv, x, cx);
    float ny = fmaf(zv, y, cy);
    float nz = fmaf(zv, z, cz);
    sns[wid][lane] = make_float4(nx, ny, nz, 0.f);
    __syncwarp();
    const float* nsrc = (const float*)sns[wid];
    unsigned nbase = (unsigned)ray * 96u;
    #pragma unroll
    for (int j = 0; j < 3; j++) {
        int e = 32 * j + lane;
        ns[nbase + e] = nsrc[e + e / 3];
    }
}

extern "C" void kernel_launch(void* const* d_in, const int* in_sizes, int n_in,
                              void* d_out, int out_size) {
    const float* rd  = (const float*)d_in[0];   // ray_dirs (1, P, 3)
    const float* cam = (const float*)d_in[1];   // cam_loc (1, 3)
    const float* tr  = (const float*)d_in[2];   // t_rand (P, 64)
    int P = in_sizes[0] / 3;

    float* out = (float*)d_out;
    float* ns  = out;                                     // (P, 32, 3)
    float* zs  = out + (size_t)P * 96;                    // (P, 32)
    float* wo  = out + (size_t)P * 96 + (size_t)P * 32;   // (P, 63)

    int rblocks = (P + 1023) / 1024;                      // 4 rays/thread
    k_reduce<<<rblocks, 256>>>(rd, cam, P);
    long long tot = (long long)P * 32;
    k_main<<<(int)((tot + 255) / 256), 256>>>(rd, cam, tr, ns, zs, wo, P);
}

// round 14
// speedup vs baseline: 1.3524x; 1.0485x over previous
#include <cuda_runtime.h>
#include <math.h>

#define FULL 0xffffffffu

// Guaranteed single-MUFU approx ops (independent of compiler fast-math flags).
__device__ __forceinline__ float fast_sqrt(float x) {
    float r; asm("sqrt.approx.f32 %0, %1;" : "=f"(r) : "f"(x)); return r;
}
__device__ __forceinline__ float fast_rcp(float x) {
    float r; asm("rcp.approx.f32 %0, %1;" : "=f"(r) : "f"(x)); return r;
}

// Global-reduction scratch. Statically zero; the k_reduce finalizer resets it
// after use so every graph replay sees the same initial state.
__device__ double g_sum0 = 0.0, g_sum1 = 0.0;
__device__ int    g_cnt = 0, g_done = 0;
__device__ float  g_mean0 = 0.f, g_mean1 = 0.f;

__device__ __forceinline__ void acc_ray(float x, float y, float z,
                                        float cx, float cy, float cz, float c2,
                                        float& s0, float& s1, int& c) {
    float dt = x * cx + y * cy + z * cz;
    float un = dt * dt - c2;
    if (un > 0.f) {
        float sq = fast_sqrt(un);
        s0 += -sq - dt; s1 += sq - dt; c++;
    }
}

// Pass 1: 4 rays/thread, float4 loads. Reduce sum(si0), sum(si1), hit count.
__global__ __launch_bounds__(256) void k_reduce(const float* __restrict__ rd,
                                                const float* __restrict__ cam, int P) {
    int i = (blockIdx.x * blockDim.x + threadIdx.x) * 4;
    float cx = cam[0], cy = cam[1], cz = cam[2];
    float c2 = cx * cx + cy * cy + cz * cz - 1.0f;  // R_SPHERE = 1
    float s0 = 0.f, s1 = 0.f; int c = 0;
    if (i + 3 < P) {
        const float4* p4 = (const float4*)(rd + 3 * i);   // 48B-aligned (16 | 48i)
        float4 A = p4[0], B = p4[1], C = p4[2];
        acc_ray(A.x, A.y, A.z, cx, cy, cz, c2, s0, s1, c);
        acc_ray(A.w, B.x, B.y, cx, cy, cz, c2, s0, s1, c);
        acc_ray(B.z, B.w, C.x, cx, cy, cz, c2, s0, s1, c);
        acc_ray(C.y, C.z, C.w, cx, cy, cz, c2, s0, s1, c);
    } else {
        for (int r = 0; r < 4 && i + r < P; r++) {
            int ii = i + r;
            acc_ray(rd[3*ii], rd[3*ii+1], rd[3*ii+2], cx, cy, cz, c2, s0, s1, c);
        }
    }
    #pragma unroll
    for (int d = 16; d; d >>= 1) {
        s0 += __shfl_down_sync(FULL, s0, d);
        s1 += __shfl_down_sync(FULL, s1, d);
        c  += __shfl_down_sync(FULL, c, d);
    }
    __shared__ float sh0[8], sh1[8]; __shared__ int shc[8];
    int w = threadIdx.x >> 5, ln = threadIdx.x & 31;
    if (ln == 0) { sh0[w] = s0; sh1[w] = s1; shc[w] = c; }
    __syncthreads();
    if (threadIdx.x == 0) {
        float a0 = 0.f, a1 = 0.f; int ac = 0;
        #pragma unroll
        for (int j = 0; j < 8; j++) { a0 += sh0[j]; a1 += sh1[j]; ac += shc[j]; }
        atomicAdd(&g_sum0, (double)a0);
        atomicAdd(&g_sum1, (double)a1);
        atomicAdd(&g_cnt, ac);
        __threadfence();
        int t = atomicAdd(&g_done, 1);
        if (t == (int)gridDim.x - 1) {
            double t0 = atomicAdd(&g_sum0, 0.0);
            double t1 = atomicAdd(&g_sum1, 0.0);
            int    nc = atomicAdd(&g_cnt, 0);
            int nh = nc > 0 ? nc : 1;
            g_mean0 = (float)(t0 / (double)nh);
            g_mean1 = (float)(t1 / (double)nh);
            __threadfence();
            g_sum0 = 0.0; g_sum1 = 0.0; g_cnt = 0; g_done = 0;  // reset for next replay
        }
    }
}

// Pass 2: one warp per ray. Lane l owns steps {2l, 2l+1}.
__global__ __launch_bounds__(256) void k_main(const float* __restrict__ rd,
                                              const float* __restrict__ cam,
                                              const float* __restrict__ trand,
                                              float* __restrict__ ns,
                                              float* __restrict__ zs,
                                              float* __restrict__ wout, int P) {
    __shared__ float2 scum[8][32];   // per-warp cum[64] (2/lane)
    __shared__ float2 sstp[8][32];   // per-warp steps[64]

    int gt   = blockIdx.x * blockDim.x + threadIdx.x;
    int ray  = gt >> 5;
    int lane = gt & 31;
    int wid  = (threadIdx.x >> 5);
    if (ray >= P) return;

    float cx = cam[0], cy = cam[1], cz = cam[2];
    float cc = cx * cx + cy * cy + cz * cz;   // |cam|^2
    float c2 = cc - 1.0f;                     // R_SPHERE = 1
    float x = rd[3 * ray + 0], y = rd[3 * ray + 1], z = rd[3 * ray + 2];
    float dt = x * cx + y * cy + z * cz;
    float un = dt * dt - c2;

    float si0, si1;
    if (un > 0.f) {
        float sq = fast_sqrt(un);
        si0 = -sq - dt; si1 = sq - dt;
    } else {
        si0 = g_mean0;
        si1 = g_mean1;
    }
    si0 = fmaxf(si0, 0.f); si1 = fmaxf(si1, 0.f);   // needed: away-pointing rays give negative roots
    float mind = si0;
    float rng  = si1 - si0;
    float sd   = rng * (1.0f / 64.0f);

    // steps (coalesced float2 load of t_rand)
    float2 tr = *(const float2*)(trand + (unsigned)ray * 64u + 2u * (unsigned)lane);
    int i0 = 2 * lane, i1 = 2 * lane + 1;
    float st0 = mind + ((float)i0 * (1.0f / 63.0f)) * rng + (tr.x - 0.5f) * sd;
    float st1 = mind + ((float)i1 * (1.0f / 63.0f)) * rng + (tr.y - 0.5f) * sd;

    // SDF via |cam + t*d|^2 = t^2 + 2t*(d.cam) + |cam|^2  (d is unit-norm)
    float dt2 = dt + dt;
    float s_0 = fast_sqrt(fmaf(st0, st0 + dt2, cc)) - 0.5f;
    float s_1 = fast_sqrt(fmaf(st1, st1 + dt2, cc)) - 0.5f;

    // alpha via sigmoid-ratio identity:
    //   alpha_k = (sig_k - sig_{k+1}) / sig_k = (E_{k+1} - E_k) / (1 + E_{k+1}),
    //   E = exp(-sdf * inv_s). Ratio provably < 1, so only clamp at 0.
    const float inv_s = 20.085536923187668f;  // exp(0.3 * 10)
    float E0 = __expf(-s_0 * inv_s);
    float E1 = __expf(-s_1 * inv_s);
    float En = __shfl_down_sync(FULL, E0, 1);  // E of step 2l+2
    float a0 = fmaxf(__fdividef(E1 - E0, 1.0f + E1), 0.f);
    float a1 = (lane < 31) ? fmaxf(__fdividef(En - E1, 1.0f + En), 0.f) : 0.f;

    float g0 = 1.0f - a0 + 1e-7f;
    float g1 = (lane < 31) ? (1.0f - a1 + 1e-7f) : 1.0f;

    // exclusive prefix-product across warp of per-lane pair product
    float pi = g0 * g1;
    #pragma unroll
    for (int d = 1; d < 32; d <<= 1) {
        float v = __shfl_up_sync(FULL, pi, d);
        if (lane >= d) pi *= v;
    }
    float Pex = __shfl_up_sync(FULL, pi, 1);
    if (lane == 0) Pex = 1.0f;

    float w0 = a0 * Pex;            // weights[2l]
    float w1 = a1 * (Pex * g0);     // weights[2l+1] (unused for lane 31)

    // unnormalized CDF (cumsum of w + 1e-8); element 63 contributes 0
    float e0 = w0 + 1e-8f;
    float e1 = (lane < 31) ? (w1 + 1e-8f) : 0.f;
    float qi = e0 + e1;
    #pragma unroll
    for (int d = 1; d < 32; d <<= 1) {
        float v = __shfl_up_sync(FULL, qi, d);
        if (lane >= d) qi += v;
    }
    float cum0  = qi - e1;                   // cumw[2l]
    float cum1  = qi;                        // cumw[2l+1]
    float total = __shfl_sync(FULL, qi, 31);

    // stash cum + steps in smem for the search
    scum[wid][lane] = make_float2(cum0, cum1);
    sstp[wid][lane] = make_float2(st0, st1);
    __syncwarp();
    const float* cumA = (const float*)scum[wid];
    const float* stpA = (const float*)sstp[wid];

    // write weights (63 per ray)
    unsigned wbase = (unsigned)ray * 63u;
    wout[wbase + i0] = w0;
    if (lane < 31) wout[wbase + i1] = w1;

    // importance sample: one u per lane, u = (2l+1)/64
    float u  = (float)(2 * lane + 1) * (1.0f / 64.0f);
    float uT = u * total;

    // c = count of cumw[k] <= uT, k in [0,63). cumA[62]=total > uT => c <= 62,
    // and k=c+s-1 <= 62 on every search iteration: no bounds guards needed.
    int c = 0;
    #pragma unroll
    for (int s = 32; s; s >>= 1) {
        if (cumA[c + s - 1] <= uT) c += s;
    }
    int   ab   = c + 1;                      // <= 63, no clamp needed
    float rtot = fast_rcp(total);
    float cdfb = (c == 0) ? 0.f : cumA[c - 1] * rtot;
    float cdfa = cumA[ab - 1] * rtot;
    float binb = stpA[c];
    float bina = stpA[ab];
    float den  = cdfa - cdfb;
    den = (den < 1e-8f) ? 1.0f : den;
    float zv = binb + __fdividef(u - cdfb, den) * (bina - binb);

    // z_samples (coalesced)
    zs[(unsigned)ray * 32u + (unsigned)lane] = zv;

    // new_samples: direct per-lane stores of own sample (3 consecutive floats,
    // warp covers 384 contiguous bytes per STG -> 3 wavefronts each, 9 total).
    unsigned nb = (unsigned)ray * 96u + (unsigned)lane * 3u;
    ns[nb + 0] = fmaf(zv, x, cx);
    ns[nb + 1] = fmaf(zv, y, cy);
    ns[nb + 2] = fmaf(zv, z, cz);
}

extern "C" void kernel_launch(void* const* d_in, const int* in_sizes, int n_in,
                              void* d_out, int out_size) {
    const float* rd  = (const float*)d_in[0];   // ray_dirs (1, P, 3)
    const float* cam = (const float*)d_in[1];   // cam_loc (1, 3)
    const float* tr  = (const float*)d_in[2];   // t_rand (P, 64)
    int P = in_sizes[0] / 3;

    float* out = (float*)d_out;
    float* ns  = out;                                     // (P, 32, 3)
    float* zs  = out + (size_t)P * 96;                    // (P, 32)
    float* wo  = out + (size_t)P * 96 + (size_t)P * 32;   // (P, 63)

    int rblocks = (P + 1023) / 1024;                      // 4 rays/thread
    k_reduce<<<rblocks, 256>>>(rd, cam, P);
    long long tot = (long long)P * 32;
    k_main<<<(int)((tot + 255) / 256), 256>>>(rd, cam, tr, ns, zs, wo, P);
}

// round 15
// speedup vs baseline: 1.3556x; 1.0024x over previous
#include <cuda_runtime.h>
#include <math.h>

#define FULL 0xffffffffu

// Guaranteed single-MUFU approx ops (independent of compiler fast-math flags).
__device__ __forceinline__ float fast_sqrt(float x) {
    float r; asm("sqrt.approx.f32 %0, %1;" : "=f"(r) : "f"(x)); return r;
}
__device__ __forceinline__ float fast_rcp(float x) {
    float r; asm("rcp.approx.f32 %0, %1;" : "=f"(r) : "f"(x)); return r;
}

// Global-reduction scratch. Statically zero; the k_reduce finalizer resets it
// after use so every graph replay sees the same initial state.
__device__ double g_sum0 = 0.0, g_sum1 = 0.0;
__device__ int    g_cnt = 0, g_done = 0;
__device__ float  g_mean0 = 0.f, g_mean1 = 0.f;

__device__ __forceinline__ void acc_ray(float x, float y, float z,
                                        float cx, float cy, float cz, float c2,
                                        float& s0, float& s1, int& c) {
    float dt = x * cx + y * cy + z * cz;
    float un = dt * dt - c2;
    if (un > 0.f) {
        float sq = fast_sqrt(un);
        s0 += -sq - dt; s1 += sq - dt; c++;
    }
}

// Pass 1: 8 rays/thread, float4 loads. Reduce sum(si0), sum(si1), hit count.
__global__ __launch_bounds__(256) void k_reduce(const float* __restrict__ rd,
                                                const float* __restrict__ cam, int P) {
    int i = (blockIdx.x * blockDim.x + threadIdx.x) * 8;
    float cx = cam[0], cy = cam[1], cz = cam[2];
    float c2 = cx * cx + cy * cy + cz * cz - 1.0f;  // R_SPHERE = 1
    float s0 = 0.f, s1 = 0.f; int c = 0;
    if (i + 7 < P) {
        const float4* p4 = (const float4*)(rd + 3 * i);   // 24 floats = 6 float4
        float4 A = p4[0], B = p4[1], C = p4[2], D = p4[3], E = p4[4], F = p4[5];
        acc_ray(A.x, A.y, A.z, cx, cy, cz, c2, s0, s1, c);
        acc_ray(A.w, B.x, B.y, cx, cy, cz, c2, s0, s1, c);
        acc_ray(B.z, B.w, C.x, cx, cy, cz, c2, s0, s1, c);
        acc_ray(C.y, C.z, C.w, cx, cy, cz, c2, s0, s1, c);
        acc_ray(D.x, D.y, D.z, cx, cy, cz, c2, s0, s1, c);
        acc_ray(D.w, E.x, E.y, cx, cy, cz, c2, s0, s1, c);
        acc_ray(E.z, E.w, F.x, cx, cy, cz, c2, s0, s1, c);
        acc_ray(F.y, F.z, F.w, cx, cy, cz, c2, s0, s1, c);
    } else {
        for (int r = 0; r < 8 && i + r < P; r++) {
            int ii = i + r;
            acc_ray(rd[3*ii], rd[3*ii+1], rd[3*ii+2], cx, cy, cz, c2, s0, s1, c);
        }
    }
    #pragma unroll
    for (int d = 16; d; d >>= 1) {
        s0 += __shfl_down_sync(FULL, s0, d);
        s1 += __shfl_down_sync(FULL, s1, d);
        c  += __shfl_down_sync(FULL, c, d);
    }
    __shared__ float sh0[8], sh1[8]; __shared__ int shc[8];
    int w = threadIdx.x >> 5, ln = threadIdx.x & 31;
    if (ln == 0) { sh0[w] = s0; sh1[w] = s1; shc[w] = c; }
    __syncthreads();
    if (threadIdx.x == 0) {
        float a0 = 0.f, a1 = 0.f; int ac = 0;
        #pragma unroll
        for (int j = 0; j < 8; j++) { a0 += sh0[j]; a1 += sh1[j]; ac += shc[j]; }
        atomicAdd(&g_sum0, (double)a0);
        atomicAdd(&g_sum1, (double)a1);
        atomicAdd(&g_cnt, ac);
        __threadfence();
        int t = atomicAdd(&g_done, 1);
        if (t == (int)gridDim.x - 1) {
            double t0 = atomicAdd(&g_sum0, 0.0);
            double t1 = atomicAdd(&g_sum1, 0.0);
            int    nc = atomicAdd(&g_cnt, 0);
            int nh = nc > 0 ? nc : 1;
            g_mean0 = (float)(t0 / (double)nh);
            g_mean1 = (float)(t1 / (double)nh);
            __threadfence();
            g_sum0 = 0.0; g_sum1 = 0.0; g_cnt = 0; g_done = 0;  // reset for next replay
        }
    }
}

// Pass 2: one warp per ray. Lane l owns steps {2l, 2l+1}.
__global__ __launch_bounds__(256) void k_main(const float* __restrict__ rd,
                                              const float* __restrict__ cam,
                                              const float* __restrict__ trand,
                                              float* __restrict__ ns,
                                              float* __restrict__ zs,
                                              float* __restrict__ wout, int P) {
    __shared__ float2 scum[8][32];   // per-warp cum[64] (2/lane)
    __shared__ float2 sstp[8][32];   // per-warp steps[64]

    int gt   = blockIdx.x * blockDim.x + threadIdx.x;
    int ray  = gt >> 5;
    int lane = gt & 31;
    int wid  = (threadIdx.x >> 5);
    if (ray >= P) return;

    float cx = cam[0], cy = cam[1], cz = cam[2];
    float cc = cx * cx + cy * cy + cz * cz;   // |cam|^2
    float c2 = cc - 1.0f;                     // R_SPHERE = 1
    float x = rd[3 * ray + 0], y = rd[3 * ray + 1], z = rd[3 * ray + 2];
    float dt = x * cx + y * cy + z * cz;
    float un = dt * dt - c2;

    float si0, si1;
    if (un > 0.f) {
        float sq = fast_sqrt(un);
        si0 = -sq - dt; si1 = sq - dt;
    } else {
        si0 = g_mean0;
        si1 = g_mean1;
    }
    si0 = fmaxf(si0, 0.f); si1 = fmaxf(si1, 0.f);   // away-pointing rays give negative roots
    float mind = si0;
    float rng  = si1 - si0;
    float sd   = rng * (1.0f / 64.0f);

    // steps: st_i = A + i*B + tr*sd, with A = mind - 0.5*sd, B = rng/63
    float B = rng * (1.0f / 63.0f);
    float A = fmaf(sd, -0.5f, mind);
    float2 tr = *(const float2*)(trand + (unsigned)ray * 64u + 2u * (unsigned)lane);
    int i0 = 2 * lane, i1 = 2 * lane + 1;
    float st0 = fmaf(tr.x, sd, fmaf((float)i0, B, A));
    float st1 = fmaf(tr.y, sd, fmaf((float)i1, B, A));

    // SDF via |cam + t*d|^2 = t^2 + 2t*(d.cam) + |cam|^2  (d is unit-norm)
    float dt2 = dt + dt;
    float s_0 = fast_sqrt(fmaf(st0, st0 + dt2, cc)) - 0.5f;
    float s_1 = fast_sqrt(fmaf(st1, st1 + dt2, cc)) - 0.5f;

    // alpha via sigmoid-ratio identity:
    //   alpha_k = (E_{k+1} - E_k) / (1 + E_{k+1}),  E = exp(-sdf * inv_s).
    const float inv_s = 20.085536923187668f;  // exp(0.3 * 10)
    float E0 = __expf(-s_0 * inv_s);
    float E1 = __expf(-s_1 * inv_s);
    float En = __shfl_down_sync(FULL, E0, 1);  // E of step 2l+2
    float a0 = fmaxf(__fdividef(E1 - E0, 1.0f + E1), 0.f);
    float a1 = (lane < 31) ? fmaxf(__fdividef(En - E1, 1.0f + En), 0.f) : 0.f;

    float g0 = 1.0f - a0 + 1e-7f;
    float g1 = (lane < 31) ? (1.0f - a1 + 1e-7f) : 1.0f;

    // exclusive prefix-product across warp of per-lane pair product
    float pi = g0 * g1;
    #pragma unroll
    for (int d = 1; d < 32; d <<= 1) {
        float v = __shfl_up_sync(FULL, pi, d);
        if (lane >= d) pi *= v;
    }
    float Pex = __shfl_up_sync(FULL, pi, 1);
    if (lane == 0) Pex = 1.0f;

    float w0 = a0 * Pex;            // weights[2l]
    float w1 = a1 * (Pex * g0);     // weights[2l+1] (unused for lane 31)

    // unnormalized CDF (cumsum of w + 1e-8); element 63 contributes 0
    float e0 = w0 + 1e-8f;
    float e1 = (lane < 31) ? (w1 + 1e-8f) : 0.f;
    float qi = e0 + e1;
    #pragma unroll
    for (int d = 1; d < 32; d <<= 1) {
        float v = __shfl_up_sync(FULL, qi, d);
        if (lane >= d) qi += v;
    }
    float cum0  = qi - e1;                   // cumw[2l]
    float cum1  = qi;                        // cumw[2l+1]
    float total = __shfl_sync(FULL, qi, 31);

    // stash cum + steps in smem for the search
    scum[wid][lane] = make_float2(cum0, cum1);
    sstp[wid][lane] = make_float2(st0, st1);
    __syncwarp();
    const float* cumA = (const float*)scum[wid];
    const float* stpA = (const float*)sstp[wid];

    // write weights (63 per ray). wbase is 8B-aligned iff ray is even:
    // even rays use one float2 store per lane (+ scalar tail from lane 31).
    unsigned wbase = (unsigned)ray * 63u;
    if ((ray & 1) == 0) {
        if (lane < 31) *(float2*)(wout + wbase + (unsigned)i0) = make_float2(w0, w1);
        else           wout[wbase + 62u] = w0;
    } else {
        wout[wbase + (unsigned)i0] = w0;
        if (lane < 31) wout[wbase + (unsigned)i1] = w1;
    }

    // importance sample: one u per lane, u = (2l+1)/64
    float u  = (float)(2 * lane + 1) * (1.0f / 64.0f);
    float uT = u * total;

    // c = count of cumw[k] <= uT, k in [0,63). cumA[62]=total > uT => c <= 62,
    // and k=c+s-1 <= 62 on every search iteration: no bounds guards needed.
    int c = 0;
    #pragma unroll
    for (int s = 32; s; s >>= 1) {
        if (cumA[c + s - 1] <= uT) c += s;
    }
    int   ab   = c + 1;                      // <= 63, no clamp needed
    float rtot = fast_rcp(total);
    float cdfb = (c == 0) ? 0.f : cumA[c - 1] * rtot;
    float cdfa = cumA[ab - 1] * rtot;
    float binb = stpA[c];
    float bina = stpA[ab];
    float den  = cdfa - cdfb;
    den = (den < 1e-8f) ? 1.0f : den;
    float zv = binb + __fdividef(u - cdfb, den) * (bina - binb);

    // z_samples (coalesced)
    zs[(unsigned)ray * 32u + (unsigned)lane] = zv;

    // new_samples: direct per-lane stores of own sample (3 consecutive floats).
    unsigned nb = (unsigned)ray * 96u + (unsigned)lane * 3u;
    ns[nb + 0] = fmaf(zv, x, cx);
    ns[nb + 1] = fmaf(zv, y, cy);
    ns[nb + 2] = fmaf(zv, z, cz);
}

extern "C" void kernel_launch(void* const* d_in, const int* in_sizes, int n_in,
                              void* d_out, int out_size) {
    const float* rd  = (const float*)d_in[0];   // ray_dirs (1, P, 3)
    const float* cam = (const float*)d_in[1];   // cam_loc (1, 3)
    const float* tr  = (const float*)d_in[2];   // t_rand (P, 64)
    int P = in_sizes[0] / 3;

    float* out = (float*)d_out;
    float* ns  = out;                                     // (P, 32, 3)
    float* zs  = out + (size_t)P * 96;                    // (P, 32)
    float* wo  = out + (size_t)P * 96 + (size_t)P * 32;   // (P, 63)

    int rblocks = (P + 2047) / 2048;                      // 8 rays/thread
    k_reduce<<<rblocks, 256>>>(rd, cam, P);
    long long tot = (long long)P * 32;
    k_main<<<(int)((tot + 255) / 256), 256>>>(rd, cam, tr, ns, zs, wo, P);
}

// round 17
// speedup vs baseline: 1.6500x; 1.2172x over previous
#include <cuda_runtime.h>
#include <math.h>

#define FULL 0xffffffffu

// Guaranteed single-MUFU approx ops (independent of compiler fast-math flags).
__device__ __forceinline__ float fast_sqrt(float x) {
    float r; asm("sqrt.approx.f32 %0, %1;" : "=f"(r) : "f"(x)); return r;
}
__device__ __forceinline__ float fast_rcp(float x) {
    float r; asm("rcp.approx.f32 %0, %1;" : "=f"(r) : "f"(x)); return r;
}

// Global-reduction scratch. Statically zero; the k_reduce finalizer resets it
// after use so every graph replay sees the same initial state.
__device__ double g_sum0 = 0.0, g_sum1 = 0.0;
__device__ int    g_cnt = 0, g_done = 0;
__device__ float  g_mean0 = 0.f, g_mean1 = 0.f;

__device__ __forceinline__ void acc_ray(float x, float y, float z,
                                        float cx, float cy, float cz, float c2,
                                        float& s0, float& s1, int& c) {
    float dt = x * cx + y * cy + z * cz;
    float un = dt * dt - c2;
    if (un > 0.f) {
        float sq = fast_sqrt(un);
        s0 += -sq - dt; s1 += sq - dt; c++;
    }
}

// Pass 1: 8 rays/thread, float4 loads. Reduce sum(si0), sum(si1), hit count.
__global__ __launch_bounds__(256) void k_reduce(const float* __restrict__ rd,
                                                const float* __restrict__ cam, int P) {
    int i = (blockIdx.x * blockDim.x + threadIdx.x) * 8;
    float cx = cam[0], cy = cam[1], cz = cam[2];
    float c2 = cx * cx + cy * cy + cz * cz - 1.0f;  // R_SPHERE = 1
    float s0 = 0.f, s1 = 0.f; int c = 0;
    if (i + 7 < P) {
        const float4* p4 = (const float4*)(rd + 3 * i);   // 24 floats = 6 float4
        float4 A = p4[0], B = p4[1], C = p4[2], D = p4[3], E = p4[4], F = p4[5];
        acc_ray(A.x, A.y, A.z, cx, cy, cz, c2, s0, s1, c);
        acc_ray(A.w, B.x, B.y, cx, cy, cz, c2, s0, s1, c);
        acc_ray(B.z, B.w, C.x, cx, cy, cz, c2, s0, s1, c);
        acc_ray(C.y, C.z, C.w, cx, cy, cz, c2, s0, s1, c);
        acc_ray(D.x, D.y, D.z, cx, cy, cz, c2, s0, s1, c);
        acc_ray(D.w, E.x, E.y, cx, cy, cz, c2, s0, s1, c);
        acc_ray(E.z, E.w, F.x, cx, cy, cz, c2, s0, s1, c);
        acc_ray(F.y, F.z, F.w, cx, cy, cz, c2, s0, s1, c);
    } else {
        for (int r = 0; r < 8 && i + r < P; r++) {
            int ii = i + r;
            acc_ray(rd[3*ii], rd[3*ii+1], rd[3*ii+2], cx, cy, cz, c2, s0, s1, c);
        }
    }
    #pragma unroll
    for (int d = 16; d; d >>= 1) {
        s0 += __shfl_down_sync(FULL, s0, d);
        s1 += __shfl_down_sync(FULL, s1, d);
        c  += __shfl_down_sync(FULL, c, d);
    }
    __shared__ float sh0[8], sh1[8]; __shared__ int shc[8];
    int w = threadIdx.x >> 5, ln = threadIdx.x & 31;
    if (ln == 0) { sh0[w] = s0; sh1[w] = s1; shc[w] = c; }
    __syncthreads();
    if (threadIdx.x == 0) {
        float a0 = 0.f, a1 = 0.f; int ac = 0;
        #pragma unroll
        for (int j = 0; j < 8; j++) { a0 += sh0[j]; a1 += sh1[j]; ac += shc[j]; }
        atomicAdd(&g_sum0, (double)a0);
        atomicAdd(&g_sum1, (double)a1);
        atomicAdd(&g_cnt, ac);
        __threadfence();
        int t = atomicAdd(&g_done, 1);
        if (t == (int)gridDim.x - 1) {
            double t0 = atomicAdd(&g_sum0, 0.0);
            double t1 = atomicAdd(&g_sum1, 0.0);
            int    nc = atomicAdd(&g_cnt, 0);
            int nh = nc > 0 ? nc : 1;
            g_mean0 = (float)(t0 / (double)nh);
            g_mean1 = (float)(t1 / (double)nh);
            __threadfence();
            g_sum0 = 0.0; g_sum1 = 0.0; g_cnt = 0; g_done = 0;  // reset for next replay
        }
    }
}

// Pass 2: TWO rays per warp. Lanes 0-15 own ray 2w, lanes 16-31 own ray 2w+1.
// Each lane owns 4 steps {4sl .. 4sl+3}. Scans are width-16 segmented shuffles.
__global__ __launch_bounds__(256) void k_main(const float* __restrict__ rd,
                                              const float* __restrict__ cam,
                                              const float* __restrict__ trand,
                                              float* __restrict__ ns,
                                              float* __restrict__ zs,
                                              float* __restrict__ wout, int P) {
    __shared__ float4 scum[8][2][16];   // per warp, per half: cum[64]
    __shared__ float4 sstp[8][2][16];   // per warp, per half: steps[64]

    int tid  = threadIdx.x;
    int wIdx = tid >> 5;
    int lane = tid & 31;
    int half = lane >> 4;
    int sl   = lane & 15;
    int wray = ((int)blockIdx.x * 8 + wIdx) * 2;   // first ray of this warp
    if (wray >= P) return;          // P even => both halves valid when wray < P
    int ray  = wray + half;

    float cx = cam[0], cy = cam[1], cz = cam[2];
    float cc = cx * cx + cy * cy + cz * cz;   // |cam|^2
    float c2 = cc - 1.0f;                     // R_SPHERE = 1
    float x = rd[3 * ray + 0], y = rd[3 * ray + 1], z = rd[3 * ray + 2];
    float dt = x * cx + y * cy + z * cz;
    float un = dt * dt - c2;

    float si0, si1;
    if (un > 0.f) {
        float sq = fast_sqrt(un);
        si0 = -sq - dt; si1 = sq - dt;
    } else {
        si0 = g_mean0;
        si1 = g_mean1;
    }
    si0 = fmaxf(si0, 0.f); si1 = fmaxf(si1, 0.f);
    float mind = si0;
    float rng  = si1 - si0;
    float sd   = rng * (1.0f / 64.0f);
    float Bc   = rng * (1.0f / 63.0f);
    float Ac   = fmaf(sd, -0.5f, mind);     // st_i = Ac + i*Bc + tr_i*sd

    // t_rand: one float4 per lane; warp covers 512 contiguous bytes
    float4 tr = *(const float4*)(trand + (unsigned)ray * 64u + 4u * (unsigned)sl);
    int k0 = 4 * sl;
    float st0 = fmaf(tr.x, sd, fmaf((float)(k0 + 0), Bc, Ac));
    float st1 = fmaf(tr.y, sd, fmaf((float)(k0 + 1), Bc, Ac));
    float st2 = fmaf(tr.z, sd, fmaf((float)(k0 + 2), Bc, Ac));
    float st3 = fmaf(tr.w, sd, fmaf((float)(k0 + 3), Bc, Ac));

    // SDF via |cam + t*d|^2 = t^2 + 2t*(d.cam) + |cam|^2 ; E = exp(-sdf*inv_s)
    const float inv_s = 20.085536923187668f;  // exp(0.3 * 10)
    float dt2 = dt + dt;
    float E0 = __expf(-(fast_sqrt(fmaf(st0, st0 + dt2, cc)) - 0.5f) * inv_s);
    float E1 = __expf(-(fast_sqrt(fmaf(st1, st1 + dt2, cc)) - 0.5f) * inv_s);
    float E2 = __expf(-(fast_sqrt(fmaf(st2, st2 + dt2, cc)) - 0.5f) * inv_s);
    float E3 = __expf(-(fast_sqrt(fmaf(st3, st3 + dt2, cc)) - 0.5f) * inv_s);
    float En = __shfl_down_sync(FULL, E0, 1);  // E of step 4sl+4 (unused at sl=15)

    // alpha_k = (E_{k+1} - E_k) / (1 + E_{k+1}); clamp at 0 only (ratio < 1)
    float a0 = fmaxf(__fdividef(E1 - E0, 1.0f + E1), 0.f);
    float a1 = fmaxf(__fdividef(E2 - E1, 1.0f + E2), 0.f);
    float a2 = fmaxf(__fdividef(E3 - E2, 1.0f + E3), 0.f);
    float a3 = (sl < 15) ? fmaxf(__fdividef(En - E3, 1.0f + En), 0.f) : 0.f;

    float g0 = 1.0f - a0 + 1e-7f;
    float g1 = 1.0f - a1 + 1e-7f;
    float g2 = 1.0f - a2 + 1e-7f;
    float g3 = (sl < 15) ? (1.0f - a3 + 1e-7f) : 1.0f;   // step 63 has no alpha

    // segmented (width 16) exclusive prefix-product of per-lane 4-products
    float pi = (g0 * g1) * (g2 * g3);
    #pragma unroll
    for (int d = 1; d < 16; d <<= 1) {
        float v = __shfl_up_sync(FULL, pi, d, 16);
        if (sl >= d) pi *= v;
    }
    float Pex = __shfl_up_sync(FULL, pi, 1, 16);
    if (sl == 0) Pex = 1.0f;

    // expand: transmittance at each of the 4 owned steps
    float w0 = a0 * Pex;
    float T1 = Pex * g0;  float w1 = a1 * T1;
    float T2 = T1 * g1;   float w2 = a2 * T2;
    float T3 = T2 * g2;   float w3 = a3 * T3;

    // unnormalized CDF: cumsum of (w + 1e-8); element 63 contributes 0
    float e0 = w0 + 1e-8f;
    float e1 = w1 + 1e-8f;
    float e2 = w2 + 1e-8f;
    float e3 = (sl < 15) ? (w3 + 1e-8f) : 0.f;
    float q  = ((e0 + e1) + e2) + e3;
    float qi = q;
    #pragma unroll
    for (int d = 1; d < 16; d <<= 1) {
        float v = __shfl_up_sync(FULL, qi, d, 16);
        if (sl >= d) qi += v;
    }
    float Sex = qi - q;          // exclusive start of this lane's 4 elements
    float c0 = Sex + e0;
    float c1 = c0 + e1;
    float c2s = c1 + e2;
    float c3 = c2s + e3;
    float total = __shfl_sync(FULL, qi, lane | 15);   // segment-last inclusive

    scum[wIdx][half][sl] = make_float4(c0, c1, c2s, c3);
    sstp[wIdx][half][sl] = make_float4(st0, st1, st2, st3);
    __syncwarp();
    const float* cumA = (const float*)scum[wIdx][half];
    const float* stpA = (const float*)sstp[wIdx][half];

    // weights (63 per ray): lane owns 4 (3 for sl=15)
    unsigned wbase = (unsigned)ray * 63u + (unsigned)k0;
    wout[wbase + 0] = w0;
    wout[wbase + 1] = w1;
    wout[wbase + 2] = w2;
    if (sl < 15) wout[wbase + 3] = w3;

    // importance samples: 2 per lane (sample ids 2sl, 2sl+1 of this ray's 32)
    float rtot = fast_rcp(total);
    float zv0, zv1;
    #pragma unroll
    for (int j = 0; j < 2; j++) {
        int m = 2 * sl + j;
        float u  = (float)(2 * m + 1) * (1.0f / 64.0f);
        float uT = u * total;
        // count of cumA[k] <= uT, k in [0,63). cumA[62] ~= total > uT => c <= 62.
        int c = 0;
        #pragma unroll
        for (int s = 32; s; s >>= 1) {
            if (cumA[c + s - 1] <= uT) c += s;
        }
        int   ab   = c + 1;
        float cdfb = (c == 0) ? 0.f : cumA[c - 1] * rtot;
        float cdfa = cumA[ab - 1] * rtot;
        float binb = stpA[c];
        float bina = stpA[ab];
        float den  = cdfa - cdfb;
        den = (den < 1e-8f) ? 1.0f : den;
        float zv = binb + __fdividef(u - cdfb, den) * (bina - binb);
        if (j == 0) zv0 = zv; else zv1 = zv;
    }

    // z_samples: one float2 per lane (8B aligned: (ray*32 + 2sl) even)
    *(float2*)(zs + (unsigned)ray * 32u + 2u * (unsigned)sl) = make_float2(zv0, zv1);

    // new_samples: 2 samples x 3 floats = 6 consecutive floats, as 3 float2 stores
    float n0x = fmaf(zv0, x, cx), n0y = fmaf(zv0, y, cy), n0z = fmaf(zv0, z, cz);
    float n1x = fmaf(zv1, x, cx), n1y = fmaf(zv1, y, cy), n1z = fmaf(zv1, z, cz);
    float* np = ns + (unsigned)ray * 96u + 6u * (unsigned)sl;
    *(float2*)(np + 0) = make_float2(n0x, n0y);
    *(float2*)(np + 2) = make_float2(n0z, n1x);
    *(float2*)(np + 4) = make_float2(n1y, n1z);
}

extern "C" void kernel_launch(void* const* d_in, const int* in_sizes, int n_in,
                              void* d_out, int out_size) {
    const float* rd  = (const float*)d_in[0];   // ray_dirs (1, P, 3)
    const float* cam = (const float*)d_in[1];   // cam_loc (1, 3)
    const float* tr  = (const float*)d_in[2];   // t_rand (P, 64)
    int P = in_sizes[0] / 3;

    float* out = (float*)d_out;
    float* ns  = out;                                     // (P, 32, 3)
    float* zs  = out + (size_t)P * 96;                    // (P, 32)
    float* wo  = out + (size_t)P * 96 + (size_t)P * 32;   // (P, 63)

    int rblocks = (P + 2047) / 2048;                      // 8 rays/thread
    k_reduce<<<rblocks, 256>>>(rd, cam, P);
    int mblocks = (P + 15) / 16;                          // 16 rays/block (2 per warp)
    k_main<<<mblocks, 256>>>(rd, cam, tr, ns, zs, wo, P);
}